// round 11
// baseline (speedup 1.0000x reference)
#include <cuda_runtime.h>
#include <cstdint>

// SmallRNNModel — 2-layer tanh RNN, B=64, T=512, I=256, H=512, O=256.
// Round 11: R10's distributed flag-array barrier + R5/R6's proven 513-iter
// pipelined loop timing (h0 guard i<T, h1 guard i>=1). Compute skeleton
// identical to R6 (3 groups x 128 thr, k-split 8, 8n x 4b f32x2, intra-CTA
// ksp reduce). Only the sync primitive differs from R6 -> clean A/B test.

#define T_STEPS 512
#define HID     512
#define BATCH   64
#define NCTA    128      // 16 n-tiles x 8 k-slices
#define KS      8
#define RTHREADS 384     // 3 GEMM groups x 128
#define NB      32768    // HID*BATCH
#define NBH     16384    // NB/2 (float2)

// ---------------- static device scratch ------------------------------------
__device__ float g_pre[T_STEPS * NB];        // [t][n][b]  64 MB
__device__ float g_part[2 * 3 * KS * NB];    // [parity][grp*8+ks][n][b]
__device__ float g_h0T[NB];                  // [n][b]
__device__ float g_h1T[NB];                  // [n][b]
__device__ unsigned g_flags[NCTA * 8];       // 1 flag per CTA, 32B stride

// ---------------- f32x2 helpers (bit-exact fp32) ---------------------------
__device__ __forceinline__ void upk2(uint64_t v, float& x, float& y) {
    asm("mov.b64 {%0,%1},%2;" : "=f"(x), "=f"(y) : "l"(v));
}
__device__ __forceinline__ uint64_t fma2(uint64_t a, uint64_t b, uint64_t c) {
    uint64_t d; asm("fma.rn.f32x2 %0,%1,%2,%3;" : "=l"(d) : "l"(a), "l"(b), "l"(c));
    return d;
}
__device__ __forceinline__ uint64_t add2(uint64_t a, uint64_t b) {
    uint64_t d; asm("add.rn.f32x2 %0,%1,%2;" : "=l"(d) : "l"(a), "l"(b));
    return d;
}

// ---------------- distributed flag-array grid barrier -----------------------
// Arrive: thread 0 releases this CTA's own padded flag (parallel across CTAs,
// no same-address atomic drain). Wait: threads 0..127 each acquire-poll one
// distinct CTA's flag (release/acquire pairs order the partial publishes).
__device__ __forceinline__ void flag_sync(int cta, unsigned gen) {
    __syncthreads();
    if (threadIdx.x == 0)
        asm volatile("st.release.gpu.global.u32 [%0], %1;"
                     :: "l"(g_flags + cta * 8), "r"(gen) : "memory");
    if (threadIdx.x < NCTA) {
        unsigned v;
        const unsigned* p = g_flags + threadIdx.x * 8;
        do {
            asm volatile("ld.acquire.gpu.global.u32 %0, [%1];"
                         : "=r"(v) : "l"(p) : "memory");
        } while ((int)(v - gen) < 0);
    }
    __syncthreads();
}

// ---------------- input-projection GEMM (layer 0) ---------------------------
__global__ void __launch_bounds__(256)
pre_gemm_kernel(const float* __restrict__ x,
                const float* __restrict__ W,
                const float* __restrict__ b1,
                const float* __restrict__ b2)
{
    __shared__ float As[16][68];
    __shared__ float Bs[16][68];

    const int tid = threadIdx.x;
    const int nt  = blockIdx.x;
    const int mt  = blockIdx.y;
    const int n0  = (tid >> 4) << 2;
    const int m0  = (tid & 15) << 2;
    const int lm = tid >> 2;
    const int lk = (tid & 3) << 2;

    const int arow = (lm * 512 + mt) * 256;
    const float* wrow = W + (nt * 64 + lm) * 256;

    float acc[4][4] = {};
    for (int k0 = 0; k0 < 256; k0 += 16) {
        float4 av = *(const float4*)(x + arow + k0 + lk);
        float4 wv = *(const float4*)(wrow + k0 + lk);
        As[lk + 0][lm] = av.x; As[lk + 1][lm] = av.y;
        As[lk + 2][lm] = av.z; As[lk + 3][lm] = av.w;
        Bs[lk + 0][lm] = wv.x; Bs[lk + 1][lm] = wv.y;
        Bs[lk + 2][lm] = wv.z; Bs[lk + 3][lm] = wv.w;
        __syncthreads();
        #pragma unroll
        for (int kk = 0; kk < 16; kk++) {
            float4 a = *(const float4*)&As[kk][m0];
            float4 w = *(const float4*)&Bs[kk][n0];
            float am[4] = {a.x, a.y, a.z, a.w};
            float wn[4] = {w.x, w.y, w.z, w.w};
            #pragma unroll
            for (int i = 0; i < 4; i++)
                #pragma unroll
                for (int j = 0; j < 4; j++)
                    acc[i][j] += am[i] * wn[j];
        }
        __syncthreads();
    }

    const int nbase = nt * 64 + n0;
    #pragma unroll
    for (int c = 0; c < 4; c++) {
        float bs = b1[nbase + c] + b2[nbase + c];
        float4 o = make_float4(acc[0][c] + bs, acc[1][c] + bs,
                               acc[2][c] + bs, acc[3][c] + bs);
        *(float4*)&g_pre[mt * NB + (nbase + c) * 64 + m0] = o;   // [t][n][b]
    }
}

// ---------------- fused persistent two-layer recurrence ---------------------
// CTA (nt, ks): per matrix, n in [32nt,32nt+32), k in [64ks,64ks+64).
// Groups (128 thr): 0: h0@W_hh0 -> G0; 1: h0@W_ih1 -> Gp; 2: h1@W_hh1 -> G1.
// Pipeline timing (i = 0..T_STEPS inclusive):
//   at iter i the staged h0 is h0_out[i-1], staged h1 is h1_out[i-2];
//   P2 computes h0_out[i]   (guard i < T_STEPS, uses pre0[i] + G0)
//          and  h1_out[i-1] (guard i >= 1,      uses bias1 + Gp + G1).
__global__ void __launch_bounds__(RTHREADS, 1)
rnn_fused_kernel(const float* __restrict__ W_hh0,
                 const float* __restrict__ W_ih1,
                 const float* __restrict__ W_hh1,
                 const float* __restrict__ b_ih1,
                 const float* __restrict__ b_hh1)
{
    __shared__ float2 Wd[3][64][32];      // dup pairs {w,w}; 48 KB
    __shared__ float  hbuf[2][64][64];    // h0s, h1s; 32 KB; reused as ksp scratch
    __shared__ float2 red2[128];          // Gp sums for h1 combine

    const int tid = threadIdx.x;
    const int cta = blockIdx.x;
    const int nt  = cta >> 3;         // 0..15
    const int ks  = cta & 7;          // 0..7

    // ---- load weight slices (dup pairs, [k][n]) ----
    #pragma unroll
    for (int g = 0; g < 3; g++) {
        const float* Wsrc = (g == 0) ? W_hh0 : (g == 1) ? W_ih1 : W_hh1;
        for (int e = tid; e < 2048; e += RTHREADS) {
            int k = e & 63, n = e >> 6;
            float w = Wsrc[(nt * 32 + n) * 512 + ks * 64 + k];
            Wd[g][k][n] = make_float2(w, w);
        }
    }
    // zero the h rows this CTA stages (redundant across nt, same value)
    for (int e = tid; e < 4096; e += RTHREADS) {
        g_h0T[ks * 4096 + e] = 0.0f;
        g_h1T[ks * 4096 + e] = 0.0f;
    }

    // ---- GEMM thread constants ----
    const int grp = tid >> 7;               // 0,1,2
    const int lt  = tid & 127;
    const int b0  = (lt & 15) * 4;
    const int n0  = ((lt >> 4) & 3) * 8;
    const int ksp = lt >> 6;                // 0,1
    const float (*hs)[64] = (grp == 2) ? hbuf[1] : hbuf[0];
    const float2 (*wd)[32] = Wd[grp];
    const int sidx = (grp * 64 + (lt & 63)) * 16;    // scratch slot (16 u64)

    // ---- P2 constants ----
    const int q  = cta * 128 + (tid & 127);          // float2 output index
    const int qn = q >> 5;
    const float bias1 = b_ih1[qn] + b_hh1[qn];
    float2* h0T2 = (float2*)g_h0T;
    float2* h1T2 = (float2*)g_h1T;
    const float2* pre2 = (const float2*)g_pre;

    unsigned gen = 0;
    flag_sync(cta, ++gen);

    for (int i = 0; i <= T_STEPS; i++) {
        // ---- stage h slices: rows [64ks..+64) of [n][b] ----
        {
            const float4* s0 = (const float4*)(g_h0T + ks * 4096);
            const float4* s1 = (const float4*)(g_h1T + ks * 4096);
            float4* d0 = (float4*)hbuf[0];
            float4* d1 = (float4*)hbuf[1];
            #pragma unroll
            for (int r = 0; r < 3; r++) {
                int idx = r * RTHREADS + tid;
                if (idx < 1024) { d0[idx] = s0[idx]; d1[idx] = s1[idx]; }
            }
        }
        __syncthreads();

        // ---- GEMM: 8n x 4b x K32 per thread (f32x2 over b-pairs) ----
        uint64_t acc[2][8] = {};
        #pragma unroll 4
        for (int kk = 0; kk < 32; kk++) {
            int k = ksp * 32 + kk;
            ulonglong2 ap = *(const ulonglong2*)&hs[k][b0];
            const ulonglong2* wp = (const ulonglong2*)&wd[k][n0];
            ulonglong2 wA = wp[0], wB = wp[1], wC = wp[2], wD = wp[3];
            acc[0][0] = fma2(ap.x, wA.x, acc[0][0]);
            acc[1][0] = fma2(ap.y, wA.x, acc[1][0]);
            acc[0][1] = fma2(ap.x, wA.y, acc[0][1]);
            acc[1][1] = fma2(ap.y, wA.y, acc[1][1]);
            acc[0][2] = fma2(ap.x, wB.x, acc[0][2]);
            acc[1][2] = fma2(ap.y, wB.x, acc[1][2]);
            acc[0][3] = fma2(ap.x, wB.y, acc[0][3]);
            acc[1][3] = fma2(ap.y, wB.y, acc[1][3]);
            acc[0][4] = fma2(ap.x, wC.x, acc[0][4]);
            acc[1][4] = fma2(ap.y, wC.x, acc[1][4]);
            acc[0][5] = fma2(ap.x, wC.y, acc[0][5]);
            acc[1][5] = fma2(ap.y, wC.y, acc[1][5]);
            acc[0][6] = fma2(ap.x, wD.x, acc[0][6]);
            acc[1][6] = fma2(ap.y, wD.x, acc[1][6]);
            acc[0][7] = fma2(ap.x, wD.y, acc[0][7]);
            acc[1][7] = fma2(ap.y, wD.y, acc[1][7]);
        }

        // ---- intra-CTA ksp reduce through smem (reuses hbuf) ----
        __syncthreads();                          // all done reading h
        uint64_t* scr = (uint64_t*)hbuf;
        if (ksp == 1) {
            #pragma unroll
            for (int r = 0; r < 8; r++) {
                scr[sidx + r * 2 + 0] = acc[0][r];
                scr[sidx + r * 2 + 1] = acc[1][r];
            }
        }
        // hoist pre load for P2 (overlaps with scratch sync + barrier)
        float2 preval = make_float2(0.f, 0.f);
        if (tid < 128 && i < T_STEPS) preval = pre2[(size_t)i * NBH + q];
        __syncthreads();
        if (ksp == 0) {
            float* pb = g_part + (size_t)((i & 1) * 24 + grp * 8 + ks) * NB
                      + (nt * 32 + n0) * 64 + b0;
            #pragma unroll
            for (int r = 0; r < 8; r++) {
                uint64_t a0 = add2(acc[0][r], scr[sidx + r * 2 + 0]);
                uint64_t a1 = add2(acc[1][r], scr[sidx + r * 2 + 1]);
                float x0, x1, x2, x3;
                upk2(a0, x0, x1); upk2(a1, x2, x3);
                *(float4*)(pb + r * 64) = make_float4(x0, x1, x2, x3);
            }
        }

        flag_sync(cta, ++gen);      // partials (parity i&1) published

        // ---- P2: reduce + tanh (guarded pipeline updates) ----
        const float2* pp = (const float2*)g_part + (size_t)(i & 1) * (24 * NBH);
        float2 sG = make_float2(0.f, 0.f);
        if (tid < 128) {
            if (i < T_STEPS) {
                float2 s = preval;
                #pragma unroll
                for (int j = 0; j < KS; j++) {
                    float2 v = pp[j * NBH + q];
                    s.x += v.x; s.y += v.y;
                }
                h0T2[q] = make_float2(tanhf(s.x), tanhf(s.y));
            }
        } else if (tid < 256) {
            if (i >= 1) {
                float2 s = make_float2(bias1, bias1);
                #pragma unroll
                for (int j = 0; j < KS; j++) {
                    float2 v = pp[(KS + j) * NBH + q];
                    s.x += v.x; s.y += v.y;
                }
                red2[tid - 128] = s;
            }
        } else {
            if (i >= 1) {
                #pragma unroll
                for (int j = 0; j < KS; j++) {
                    float2 v = pp[(2 * KS + j) * NBH + q];
                    sG.x += v.x; sG.y += v.y;
                }
            }
        }
        __syncthreads();
        if (tid >= 256 && i >= 1) {
            float2 gp = red2[tid - 256];
            h1T2[q] = make_float2(tanhf(gp.x + sG.x), tanhf(gp.y + sG.y));
        }

        flag_sync(cta, ++gen);      // h buffers published
    }
}

// ---------------- final FC ---------------------------------------------------
__global__ void __launch_bounds__(256)
fc_kernel(const float* __restrict__ Wfc, const float* __restrict__ bfc,
          float* __restrict__ out)
{
    int idx = blockIdx.x * 256 + threadIdx.x;
    int o = idx >> 6;
    int b = idx & 63;
    const float* wr = Wfc + o * 512;
    float s = bfc[o];
    #pragma unroll 8
    for (int h = 0; h < 512; h++)
        s += g_h1T[h * 64 + b] * __ldg(&wr[h]);
    out[b * 256 + o] = s;
}

// ---------------- launch ------------------------------------------------------
extern "C" void kernel_launch(void* const* d_in, const int* in_sizes, int n_in,
                              void* d_out, int out_size)
{
    const float* x     = (const float*)d_in[0];
    const float* W_ih0 = (const float*)d_in[1];
    const float* W_hh0 = (const float*)d_in[2];
    const float* b_ih0 = (const float*)d_in[3];
    const float* b_hh0 = (const float*)d_in[4];
    const float* W_ih1 = (const float*)d_in[5];
    const float* W_hh1 = (const float*)d_in[6];
    const float* b_ih1 = (const float*)d_in[7];
    const float* b_hh1 = (const float*)d_in[8];
    const float* W_fc  = (const float*)d_in[9];
    const float* b_fc  = (const float*)d_in[10];
    float* out = (float*)d_out;

    pre_gemm_kernel<<<dim3(8, 512), 256>>>(x, W_ih0, b_ih0, b_hh0);
    rnn_fused_kernel<<<NCTA, RTHREADS>>>(W_hh0, W_ih1, W_hh1, b_ih1, b_hh1);
    fc_kernel<<<64, 256>>>(W_fc, b_fc, out);
}

// round 13
// speedup vs baseline: 1.1886x; 1.1886x over previous
#include <cuda_runtime.h>
#include <cstdint>

// SmallRNNModel — 2-layer tanh RNN, B=64, T=512, I=256, H=512, O=256.
// Round 13: R12's point-to-point producer/consumer sync with the staging
// bug fixed (h1s now fully staged: overlapping tid ranges like R5).
// Launch order rotated (pre, rnn, fc, init) so ncu -s 5 -c 1 captures the
// recurrence kernel; init_kernel (at the end) resets flags/h for the NEXT
// replay — first call is safe because device globals are zero-initialized.

#define T_STEPS 512
#define NCTA    128      // nt = cta&7 (8 n-tiles of 64), ks = cta>>3 (16 k-slices of 32)
#define KSPLIT  16
#define RTHREADS 768     // 3 GEMM groups x 256
#define NB      32768    // HID*BATCH
#define PARTN   (3 * KSPLIT * NB)

// ---------------- static device scratch ------------------------------------
__device__ float g_pre[T_STEPS * NB];     // [t][n][b]  64 MB
__device__ float g_part[2 * PARTN];       // [parity][grp*16+ks][n][b]
__device__ float g_h0T[2 * NB];           // [parity][n][b]
__device__ float g_h1T[2 * NB];
__device__ unsigned g_flagsP[NCTA * 8];   // partials-published counter, 32B stride
__device__ unsigned g_flagsH[NCTA * 8];   // h-published counter

// ---------------- sync primitives -------------------------------------------
__device__ __forceinline__ void poll_ge(const unsigned* p, int thr) {
    if (thr <= 0) return;                      // flags start at 0 each replay
    unsigned v;
    do {
        asm volatile("ld.acquire.gpu.global.u32 %0, [%1];"
                     : "=r"(v) : "l"(p) : "memory");
    } while ((int)v < thr);
}
__device__ __forceinline__ void publish(unsigned* p, int val) {
    asm volatile("st.release.gpu.global.u32 [%0], %1;"
                 :: "l"(p), "r"((unsigned)val) : "memory");
}

// ---------------- init/reset kernel (runs LAST in each launch) --------------
__global__ void __launch_bounds__(256)
init_kernel()
{
    int g = blockIdx.x * 256 + threadIdx.x;    // 0 .. 65535 (= 2*NB)
    g_h0T[g] = 0.0f;
    g_h1T[g] = 0.0f;
    if (g < NCTA * 8) { g_flagsP[g] = 0; g_flagsH[g] = 0; }
}

// ---------------- input-projection GEMM (layer 0) ---------------------------
// g_pre[t][n][b] = sum_k x[b][t][k]*W_ih0[n][k] + b_ih0[n] + b_hh0[n]
__global__ void __launch_bounds__(256)
pre_gemm_kernel(const float* __restrict__ x,
                const float* __restrict__ W,
                const float* __restrict__ b1,
                const float* __restrict__ b2)
{
    __shared__ float As[16][68];
    __shared__ float Bs[16][68];

    const int tid = threadIdx.x;
    const int nt  = blockIdx.x;
    const int mt  = blockIdx.y;
    const int n0  = (tid >> 4) << 2;
    const int m0  = (tid & 15) << 2;
    const int lm = tid >> 2;
    const int lk = (tid & 3) << 2;

    const int arow = (lm * 512 + mt) * 256;
    const float* wrow = W + (nt * 64 + lm) * 256;

    float acc[4][4] = {};
    for (int k0 = 0; k0 < 256; k0 += 16) {
        float4 av = *(const float4*)(x + arow + k0 + lk);
        float4 wv = *(const float4*)(wrow + k0 + lk);
        As[lk + 0][lm] = av.x; As[lk + 1][lm] = av.y;
        As[lk + 2][lm] = av.z; As[lk + 3][lm] = av.w;
        Bs[lk + 0][lm] = wv.x; Bs[lk + 1][lm] = wv.y;
        Bs[lk + 2][lm] = wv.z; Bs[lk + 3][lm] = wv.w;
        __syncthreads();
        #pragma unroll
        for (int kk = 0; kk < 16; kk++) {
            float4 a = *(const float4*)&As[kk][m0];
            float4 w = *(const float4*)&Bs[kk][n0];
            float am[4] = {a.x, a.y, a.z, a.w};
            float wn[4] = {w.x, w.y, w.z, w.w};
            #pragma unroll
            for (int i = 0; i < 4; i++)
                #pragma unroll
                for (int j = 0; j < 4; j++)
                    acc[i][j] += am[i] * wn[j];
        }
        __syncthreads();
    }

    const int nbase = nt * 64 + n0;
    #pragma unroll
    for (int c = 0; c < 4; c++) {
        float bs = b1[nbase + c] + b2[nbase + c];
        float4 o = make_float4(acc[0][c] + bs, acc[1][c] + bs,
                               acc[2][c] + bs, acc[3][c] + bs);
        *(float4*)&g_pre[mt * NB + (nbase + c) * 64 + m0] = o;   // [t][n][b]
    }
}

// ---------------- f32x2 helpers (bit-exact fp32) ----------------------------
__device__ __forceinline__ uint64_t fma2(uint64_t a, uint64_t b, uint64_t c) {
    uint64_t d; asm("fma.rn.f32x2 %0,%1,%2,%3;" : "=l"(d) : "l"(a), "l"(b), "l"(c));
    return d;
}
__device__ __forceinline__ void upk2(uint64_t v, float& x, float& y) {
    asm("mov.b64 {%0,%1},%2;" : "=f"(x), "=f"(y) : "l"(v));
}

// ---------------- fused persistent two-layer recurrence ---------------------
// CTA (nt = cta&7, ks = cta>>3). Groups: 0: h0@W_hh0; 1: h0@W_ih1; 2: h1@W_hh1.
// P2: thread rlt owns (rn = 32ks + 4nt + (rlt>>6), rb = rlt&63).
// Dependency sets:
//   prodH(c)   = [8*ks, +8)        : producers of the h rows c stages
//   consP(c)   = [16*nt, +16)      : readers of c's partial rows
//   prodP(c)   = {j<<3 | (ks>>1), j=0..15} : producers of c's P2 partials
//   readersH(c)= [8*ks, +8)        : stagers of c's h rows (flagsP-gated)
__global__ void __launch_bounds__(RTHREADS, 1)
rnn_fused_kernel(const float* __restrict__ W_hh0,
                 const float* __restrict__ W_ih1,
                 const float* __restrict__ W_hh1,
                 const float* __restrict__ b_ih1,
                 const float* __restrict__ b_hh1)
{
    __shared__ float2 W0d[32][64], Wpd[32][64], W1d[32][64];   // dup pairs, 48 KB
    __shared__ float h0s[32][64], h1s[32][64];                 // 16 KB
    __shared__ float red1[256];

    const int tid = threadIdx.x;
    const int cta = blockIdx.x;
    const int nt  = cta & 7;
    const int ks  = cta >> 3;

    // weight slices: n in [64nt,64nt+64), k in [32ks,32ks+32)
    for (int e = tid; e < 2048; e += RTHREADS) {
        int n = e >> 5, k = e & 31;
        int gidx = (nt * 64 + n) * 512 + ks * 32 + k;
        float w0 = W_hh0[gidx], wp = W_ih1[gidx], w1 = W_hh1[gidx];
        W0d[k][n] = make_float2(w0, w0);
        Wpd[k][n] = make_float2(wp, wp);
        W1d[k][n] = make_float2(w1, w1);
    }

    // ---- P2 constants ----
    const int rlt   = tid & 255;
    const int n_off = rlt >> 6;
    const int rb    = rlt & 63;
    const int rn    = ks * 32 + nt * 4 + n_off;
    const float bias1 = b_ih1[rn] + b_hh1[rn];

    // ---- GEMM constants ----
    const int grp = tid >> 8;                 // 0,1,2
    const int lt  = tid & 255;
    const int n0  = (lt >> 4) << 2;
    const int b0  = (lt & 15) << 2;
    const float (*hs)[64] = (grp == 2) ? h1s : h0s;
    const float2 (*wd)[64] = (grp == 0) ? W0d : (grp == 1) ? Wpd : W1d;

    // ---- dependency flag constants ----
    const int ksg8 = ks << 3;                 // base of prodH / readersH
    const int ntpp = ks >> 1;                 // producer nt for my P2 rows
    __syncthreads();

    for (int i = 0; i <= T_STEPS; i++) {
        const int par  = i & 1;
        const int spar = (i + 1) & 1;         // parity holding h(i-1)

        // ---- WAIT1: h(i-1) producers done; my partial readers past iter i-2 ----
        if (tid < 8)        poll_ge(&g_flagsH[(ksg8 + tid) * 8], i);
        else if (tid < 24)  poll_ge(&g_flagsH[(16 * nt + tid - 8) * 8], i - 1);
        __syncthreads();

        // ---- stage h slices: rows [32ks..+32) of parity spar (overlapping split) ----
        {
            const float4* s0 = (const float4*)(g_h0T + spar * NB + ks * 2048);
            const float4* s1 = (const float4*)(g_h1T + spar * NB + ks * 2048);
            if (tid < 512)  ((float4*)h0s)[tid] = s0[tid];
            if (tid >= 256) ((float4*)h1s)[tid - 256] = s1[tid - 256];
        }
        __syncthreads();

        // ---- GEMM: 4b x 4n x K32, f32x2 over b-pairs ----
        uint64_t acc[2][4] = {};
        #pragma unroll
        for (int kk = 0; kk < 32; kk++) {
            ulonglong2 ap = *(const ulonglong2*)&hs[kk][b0];
            ulonglong2 wA = *(const ulonglong2*)&wd[kk][n0];
            ulonglong2 wB = *(const ulonglong2*)&wd[kk][n0 + 2];
            acc[0][0] = fma2(ap.x, wA.x, acc[0][0]);
            acc[1][0] = fma2(ap.y, wA.x, acc[1][0]);
            acc[0][1] = fma2(ap.x, wA.y, acc[0][1]);
            acc[1][1] = fma2(ap.y, wA.y, acc[1][1]);
            acc[0][2] = fma2(ap.x, wB.x, acc[0][2]);
            acc[1][2] = fma2(ap.y, wB.x, acc[1][2]);
            acc[0][3] = fma2(ap.x, wB.y, acc[0][3]);
            acc[1][3] = fma2(ap.y, wB.y, acc[1][3]);
        }
        // hoisted pre load for P2
        float preval = 0.0f;
        if (tid < 256 && i < T_STEPS)
            preval = g_pre[(size_t)i * NB + rn * 64 + rb];

        // ---- store partials (parity par) ----
        {
            float* pb = g_part + (size_t)par * PARTN
                      + (size_t)((grp * KSPLIT + ks) * 512 + nt * 64 + n0) * 64 + b0;
            #pragma unroll
            for (int c = 0; c < 4; c++) {
                float x0, x1, x2, x3;
                upk2(acc[0][c], x0, x1);
                upk2(acc[1][c], x2, x3);
                *(float4*)(pb + c * 64) = make_float4(x0, x1, x2, x3);
            }
        }
        __syncthreads();
        if (tid == 0) publish(&g_flagsP[cta * 8], i + 1);

        // ---- WAIT2: my P2 partials ready; my h readers past staging(i-1) ----
        if (tid < 16)       poll_ge(&g_flagsP[((tid << 3) | ntpp) * 8], i + 1);
        else if (tid < 24)  poll_ge(&g_flagsP[(ksg8 + tid - 16) * 8], i);
        __syncthreads();

        // ---- P2: reduce + tanh -> h parity par (guarded pipeline) ----
        const float* pp = g_part + (size_t)par * PARTN;
        if (tid < 256) {
            if (i < T_STEPS) {
                float s = preval;
                #pragma unroll
                for (int j = 0; j < KSPLIT; j++)
                    s += pp[(j * 512 + rn) * 64 + rb];               // G0
                g_h0T[par * NB + rn * 64 + rb] = tanhf(s);
            }
        } else if (tid >= 512) {
            if (i >= 1) {
                float s = 0.0f;
                #pragma unroll
                for (int j = 0; j < KSPLIT; j++)
                    s += pp[((2 * KSPLIT + j) * 512 + rn) * 64 + rb]; // G1
                red1[rlt] = s;
            }
        }
        float gp = 0.0f;
        if (tid >= 256 && tid < 512 && i >= 1) {
            gp = bias1;
            #pragma unroll
            for (int j = 0; j < KSPLIT; j++)
                gp += pp[((KSPLIT + j) * 512 + rn) * 64 + rb];        // Gp
        }
        __syncthreads();
        if (tid >= 256 && tid < 512 && i >= 1)
            g_h1T[par * NB + rn * 64 + rb] = tanhf(gp + red1[rlt]);

        __syncthreads();
        if (tid == 0) publish(&g_flagsH[cta * 8], i + 1);
    }
}

// ---------------- final FC (h1 final is iter 512 -> parity 0) ---------------
__global__ void __launch_bounds__(256)
fc_kernel(const float* __restrict__ Wfc, const float* __restrict__ bfc,
          float* __restrict__ out)
{
    int idx = blockIdx.x * 256 + threadIdx.x;
    int o = idx >> 6;
    int b = idx & 63;
    const float* wr = Wfc + o * 512;
    float s = bfc[o];
    #pragma unroll 8
    for (int h = 0; h < 512; h++)
        s += g_h1T[h * 64 + b] * __ldg(&wr[h]);    // parity 0 = base offset
    out[b * 256 + o] = s;
}

// ---------------- launch ------------------------------------------------------
extern "C" void kernel_launch(void* const* d_in, const int* in_sizes, int n_in,
                              void* d_out, int out_size)
{
    const float* x     = (const float*)d_in[0];
    const float* W_ih0 = (const float*)d_in[1];
    const float* W_hh0 = (const float*)d_in[2];
    const float* b_ih0 = (const float*)d_in[3];
    const float* b_hh0 = (const float*)d_in[4];
    const float* W_ih1 = (const float*)d_in[5];
    const float* W_hh1 = (const float*)d_in[6];
    const float* b_ih1 = (const float*)d_in[7];
    const float* b_hh1 = (const float*)d_in[8];
    const float* W_fc  = (const float*)d_in[9];
    const float* b_fc  = (const float*)d_in[10];
    float* out = (float*)d_out;

    // Order: pre, rnn, fc, init. init (reset) runs last — device globals are
    // zero-initialized at load, so call 1 is safe; init re-arms every replay.
    // Side effect: rnn_fused is launch #6 globally -> captured by ncu -s 5 -c 1.
    pre_gemm_kernel<<<dim3(8, 512), 256>>>(x, W_ih0, b_ih0, b_hh0);
    rnn_fused_kernel<<<NCTA, RTHREADS>>>(W_hh0, W_ih1, W_hh1, b_ih1, b_hh1);
    fc_kernel<<<64, 256>>>(W_fc, b_fc, out);
    init_kernel<<<256, 256>>>();
}

// round 14
// speedup vs baseline: 1.1917x; 1.0026x over previous
#include <cuda_runtime.h>
#include <cstdint>

// SmallRNNModel — 2-layer tanh RNN, B=64, T=512, I=256, H=512, O=256.
// Round 13: R12's point-to-point producer/consumer sync with the staging
// bug fixed (h1s now fully staged: overlapping tid ranges like R5).
// Launch order rotated (pre, rnn, fc, init) so ncu -s 5 -c 1 captures the
// recurrence kernel; init_kernel (at the end) resets flags/h for the NEXT
// replay — first call is safe because device globals are zero-initialized.

#define T_STEPS 512
#define NCTA    128      // nt = cta&7 (8 n-tiles of 64), ks = cta>>3 (16 k-slices of 32)
#define KSPLIT  16
#define RTHREADS 768     // 3 GEMM groups x 256
#define NB      32768    // HID*BATCH
#define PARTN   (3 * KSPLIT * NB)

// ---------------- static device scratch ------------------------------------
__device__ float g_pre[T_STEPS * NB];     // [t][n][b]  64 MB
__device__ float g_part[2 * PARTN];       // [parity][grp*16+ks][n][b]
__device__ float g_h0T[2 * NB];           // [parity][n][b]
__device__ float g_h1T[2 * NB];
__device__ unsigned g_flagsP[NCTA * 8];   // partials-published counter, 32B stride
__device__ unsigned g_flagsH[NCTA * 8];   // h-published counter

// ---------------- sync primitives -------------------------------------------
__device__ __forceinline__ void poll_ge(const unsigned* p, int thr) {
    if (thr <= 0) return;                      // flags start at 0 each replay
    unsigned v;
    do {
        asm volatile("ld.acquire.gpu.global.u32 %0, [%1];"
                     : "=r"(v) : "l"(p) : "memory");
    } while ((int)v < thr);
}
__device__ __forceinline__ void publish(unsigned* p, int val) {
    asm volatile("st.release.gpu.global.u32 [%0], %1;"
                 :: "l"(p), "r"((unsigned)val) : "memory");
}

// ---------------- init/reset kernel (runs LAST in each launch) --------------
__global__ void __launch_bounds__(256)
init_kernel()
{
    int g = blockIdx.x * 256 + threadIdx.x;    // 0 .. 65535 (= 2*NB)
    g_h0T[g] = 0.0f;
    g_h1T[g] = 0.0f;
    if (g < NCTA * 8) { g_flagsP[g] = 0; g_flagsH[g] = 0; }
}

// ---------------- input-projection GEMM (layer 0) ---------------------------
// g_pre[t][n][b] = sum_k x[b][t][k]*W_ih0[n][k] + b_ih0[n] + b_hh0[n]
__global__ void __launch_bounds__(256)
pre_gemm_kernel(const float* __restrict__ x,
                const float* __restrict__ W,
                const float* __restrict__ b1,
                const float* __restrict__ b2)
{
    __shared__ float As[16][68];
    __shared__ float Bs[16][68];

    const int tid = threadIdx.x;
    const int nt  = blockIdx.x;
    const int mt  = blockIdx.y;
    const int n0  = (tid >> 4) << 2;
    const int m0  = (tid & 15) << 2;
    const int lm = tid >> 2;
    const int lk = (tid & 3) << 2;

    const int arow = (lm * 512 + mt) * 256;
    const float* wrow = W + (nt * 64 + lm) * 256;

    float acc[4][4] = {};
    for (int k0 = 0; k0 < 256; k0 += 16) {
        float4 av = *(const float4*)(x + arow + k0 + lk);
        float4 wv = *(const float4*)(wrow + k0 + lk);
        As[lk + 0][lm] = av.x; As[lk + 1][lm] = av.y;
        As[lk + 2][lm] = av.z; As[lk + 3][lm] = av.w;
        Bs[lk + 0][lm] = wv.x; Bs[lk + 1][lm] = wv.y;
        Bs[lk + 2][lm] = wv.z; Bs[lk + 3][lm] = wv.w;
        __syncthreads();
        #pragma unroll
        for (int kk = 0; kk < 16; kk++) {
            float4 a = *(const float4*)&As[kk][m0];
            float4 w = *(const float4*)&Bs[kk][n0];
            float am[4] = {a.x, a.y, a.z, a.w};
            float wn[4] = {w.x, w.y, w.z, w.w};
            #pragma unroll
            for (int i = 0; i < 4; i++)
                #pragma unroll
                for (int j = 0; j < 4; j++)
                    acc[i][j] += am[i] * wn[j];
        }
        __syncthreads();
    }

    const int nbase = nt * 64 + n0;
    #pragma unroll
    for (int c = 0; c < 4; c++) {
        float bs = b1[nbase + c] + b2[nbase + c];
        float4 o = make_float4(acc[0][c] + bs, acc[1][c] + bs,
                               acc[2][c] + bs, acc[3][c] + bs);
        *(float4*)&g_pre[mt * NB + (nbase + c) * 64 + m0] = o;   // [t][n][b]
    }
}

// ---------------- f32x2 helpers (bit-exact fp32) ----------------------------
__device__ __forceinline__ uint64_t fma2(uint64_t a, uint64_t b, uint64_t c) {
    uint64_t d; asm("fma.rn.f32x2 %0,%1,%2,%3;" : "=l"(d) : "l"(a), "l"(b), "l"(c));
    return d;
}
__device__ __forceinline__ void upk2(uint64_t v, float& x, float& y) {
    asm("mov.b64 {%0,%1},%2;" : "=f"(x), "=f"(y) : "l"(v));
}

// ---------------- fused persistent two-layer recurrence ---------------------
// CTA (nt = cta&7, ks = cta>>3). Groups: 0: h0@W_hh0; 1: h0@W_ih1; 2: h1@W_hh1.
// P2: thread rlt owns (rn = 32ks + 4nt + (rlt>>6), rb = rlt&63).
// Dependency sets:
//   prodH(c)   = [8*ks, +8)        : producers of the h rows c stages
//   consP(c)   = [16*nt, +16)      : readers of c's partial rows
//   prodP(c)   = {j<<3 | (ks>>1), j=0..15} : producers of c's P2 partials
//   readersH(c)= [8*ks, +8)        : stagers of c's h rows (flagsP-gated)
__global__ void __launch_bounds__(RTHREADS, 1)
rnn_fused_kernel(const float* __restrict__ W_hh0,
                 const float* __restrict__ W_ih1,
                 const float* __restrict__ W_hh1,
                 const float* __restrict__ b_ih1,
                 const float* __restrict__ b_hh1)
{
    __shared__ float2 W0d[32][64], Wpd[32][64], W1d[32][64];   // dup pairs, 48 KB
    __shared__ float h0s[32][64], h1s[32][64];                 // 16 KB
    __shared__ float red1[256];

    const int tid = threadIdx.x;
    const int cta = blockIdx.x;
    const int nt  = cta & 7;
    const int ks  = cta >> 3;

    // weight slices: n in [64nt,64nt+64), k in [32ks,32ks+32)
    for (int e = tid; e < 2048; e += RTHREADS) {
        int n = e >> 5, k = e & 31;
        int gidx = (nt * 64 + n) * 512 + ks * 32 + k;
        float w0 = W_hh0[gidx], wp = W_ih1[gidx], w1 = W_hh1[gidx];
        W0d[k][n] = make_float2(w0, w0);
        Wpd[k][n] = make_float2(wp, wp);
        W1d[k][n] = make_float2(w1, w1);
    }

    // ---- P2 constants ----
    const int rlt   = tid & 255;
    const int n_off = rlt >> 6;
    const int rb    = rlt & 63;
    const int rn    = ks * 32 + nt * 4 + n_off;
    const float bias1 = b_ih1[rn] + b_hh1[rn];

    // ---- GEMM constants ----
    const int grp = tid >> 8;                 // 0,1,2
    const int lt  = tid & 255;
    const int n0  = (lt >> 4) << 2;
    const int b0  = (lt & 15) << 2;
    const float (*hs)[64] = (grp == 2) ? h1s : h0s;
    const float2 (*wd)[64] = (grp == 0) ? W0d : (grp == 1) ? Wpd : W1d;

    // ---- dependency flag constants ----
    const int ksg8 = ks << 3;                 // base of prodH / readersH
    const int ntpp = ks >> 1;                 // producer nt for my P2 rows
    __syncthreads();

    for (int i = 0; i <= T_STEPS; i++) {
        const int par  = i & 1;
        const int spar = (i + 1) & 1;         // parity holding h(i-1)

        // ---- WAIT1: h(i-1) producers done; my partial readers past iter i-2 ----
        if (tid < 8)        poll_ge(&g_flagsH[(ksg8 + tid) * 8], i);
        else if (tid < 24)  poll_ge(&g_flagsH[(16 * nt + tid - 8) * 8], i - 1);
        __syncthreads();

        // ---- stage h slices: rows [32ks..+32) of parity spar (overlapping split) ----
        {
            const float4* s0 = (const float4*)(g_h0T + spar * NB + ks * 2048);
            const float4* s1 = (const float4*)(g_h1T + spar * NB + ks * 2048);
            if (tid < 512)  ((float4*)h0s)[tid] = s0[tid];
            if (tid >= 256) ((float4*)h1s)[tid - 256] = s1[tid - 256];
        }
        __syncthreads();

        // ---- GEMM: 4b x 4n x K32, f32x2 over b-pairs ----
        uint64_t acc[2][4] = {};
        #pragma unroll
        for (int kk = 0; kk < 32; kk++) {
            ulonglong2 ap = *(const ulonglong2*)&hs[kk][b0];
            ulonglong2 wA = *(const ulonglong2*)&wd[kk][n0];
            ulonglong2 wB = *(const ulonglong2*)&wd[kk][n0 + 2];
            acc[0][0] = fma2(ap.x, wA.x, acc[0][0]);
            acc[1][0] = fma2(ap.y, wA.x, acc[1][0]);
            acc[0][1] = fma2(ap.x, wA.y, acc[0][1]);
            acc[1][1] = fma2(ap.y, wA.y, acc[1][1]);
            acc[0][2] = fma2(ap.x, wB.x, acc[0][2]);
            acc[1][2] = fma2(ap.y, wB.x, acc[1][2]);
            acc[0][3] = fma2(ap.x, wB.y, acc[0][3]);
            acc[1][3] = fma2(ap.y, wB.y, acc[1][3]);
        }
        // hoisted pre load for P2
        float preval = 0.0f;
        if (tid < 256 && i < T_STEPS)
            preval = g_pre[(size_t)i * NB + rn * 64 + rb];

        // ---- store partials (parity par) ----
        {
            float* pb = g_part + (size_t)par * PARTN
                      + (size_t)((grp * KSPLIT + ks) * 512 + nt * 64 + n0) * 64 + b0;
            #pragma unroll
            for (int c = 0; c < 4; c++) {
                float x0, x1, x2, x3;
                upk2(acc[0][c], x0, x1);
                upk2(acc[1][c], x2, x3);
                *(float4*)(pb + c * 64) = make_float4(x0, x1, x2, x3);
            }
        }
        __syncthreads();
        if (tid == 0) publish(&g_flagsP[cta * 8], i + 1);

        // ---- WAIT2: my P2 partials ready; my h readers past staging(i-1) ----
        if (tid < 16)       poll_ge(&g_flagsP[((tid << 3) | ntpp) * 8], i + 1);
        else if (tid < 24)  poll_ge(&g_flagsP[(ksg8 + tid - 16) * 8], i);
        __syncthreads();

        // ---- P2: reduce + tanh -> h parity par (guarded pipeline) ----
        const float* pp = g_part + (size_t)par * PARTN;
        if (tid < 256) {
            if (i < T_STEPS) {
                float s = preval;
                #pragma unroll
                for (int j = 0; j < KSPLIT; j++)
                    s += pp[(j * 512 + rn) * 64 + rb];               // G0
                g_h0T[par * NB + rn * 64 + rb] = tanhf(s);
            }
        } else if (tid >= 512) {
            if (i >= 1) {
                float s = 0.0f;
                #pragma unroll
                for (int j = 0; j < KSPLIT; j++)
                    s += pp[((2 * KSPLIT + j) * 512 + rn) * 64 + rb]; // G1
                red1[rlt] = s;
            }
        }
        float gp = 0.0f;
        if (tid >= 256 && tid < 512 && i >= 1) {
            gp = bias1;
            #pragma unroll
            for (int j = 0; j < KSPLIT; j++)
                gp += pp[((KSPLIT + j) * 512 + rn) * 64 + rb];        // Gp
        }
        __syncthreads();
        if (tid >= 256 && tid < 512 && i >= 1)
            g_h1T[par * NB + rn * 64 + rb] = tanhf(gp + red1[rlt]);

        __syncthreads();
        if (tid == 0) publish(&g_flagsH[cta * 8], i + 1);
    }
}

// ---------------- final FC (h1 final is iter 512 -> parity 0) ---------------
__global__ void __launch_bounds__(256)
fc_kernel(const float* __restrict__ Wfc, const float* __restrict__ bfc,
          float* __restrict__ out)
{
    int idx = blockIdx.x * 256 + threadIdx.x;
    int o = idx >> 6;
    int b = idx & 63;
    const float* wr = Wfc + o * 512;
    float s = bfc[o];
    #pragma unroll 8
    for (int h = 0; h < 512; h++)
        s += g_h1T[h * 64 + b] * __ldg(&wr[h]);    // parity 0 = base offset
    out[b * 256 + o] = s;
}

// ---------------- launch ------------------------------------------------------
extern "C" void kernel_launch(void* const* d_in, const int* in_sizes, int n_in,
                              void* d_out, int out_size)
{
    const float* x     = (const float*)d_in[0];
    const float* W_ih0 = (const float*)d_in[1];
    const float* W_hh0 = (const float*)d_in[2];
    const float* b_ih0 = (const float*)d_in[3];
    const float* b_hh0 = (const float*)d_in[4];
    const float* W_ih1 = (const float*)d_in[5];
    const float* W_hh1 = (const float*)d_in[6];
    const float* b_ih1 = (const float*)d_in[7];
    const float* b_hh1 = (const float*)d_in[8];
    const float* W_fc  = (const float*)d_in[9];
    const float* b_fc  = (const float*)d_in[10];
    float* out = (float*)d_out;

    // Order: pre, rnn, fc, init. init (reset) runs last — device globals are
    // zero-initialized at load, so call 1 is safe; init re-arms every replay.
    // Side effect: rnn_fused is launch #6 globally -> captured by ncu -s 5 -c 1.
    pre_gemm_kernel<<<dim3(8, 512), 256>>>(x, W_ih0, b_ih0, b_hh0);
    rnn_fused_kernel<<<NCTA, RTHREADS>>>(W_hh0, W_ih1, W_hh1, b_ih1, b_hh1);
    fc_kernel<<<64, 256>>>(W_fc, b_fc, out);
    init_kernel<<<256, 256>>>();
}